// round 10
// baseline (speedup 1.0000x reference)
#include <cuda_runtime.h>
#include <cuda_bf16.h>
#include <mma.h>
#include <cstdint>
#include <math.h>

using namespace nvcuda;

#define B_    2
#define S_    2048
#define D_    1024
#define H_    16
#define QKV_  192
#define NQKV  (H_ * QKV_)   /* 3072 */
#define MROWS (B_ * S_)     /* 4096 */

// ---------------- scratch ---------------------------------------------------
__device__ __nv_bfloat16 g_qkvhi[(size_t)MROWS * NQKV];
__device__ __nv_bfloat16 g_qkvlo[(size_t)MROWS * NQKV];
__device__ __nv_bfloat16 g_xhi[(size_t)MROWS * D_];
__device__ __nv_bfloat16 g_xlo[(size_t)MROWS * D_];
__device__ __nv_bfloat16 g_wehi[(size_t)NQKV * D_];   // [N][K]
__device__ __nv_bfloat16 g_welo[(size_t)NQKV * D_];
__device__ __nv_bfloat16 g_wohi[(size_t)D_ * D_];
__device__ __nv_bfloat16 g_wolo[(size_t)D_ * D_];
__device__ __nv_bfloat16 g_ahi[(size_t)MROWS * D_];
__device__ __nv_bfloat16 g_alo[(size_t)MROWS * D_];
__device__ float g_y[(size_t)MROWS * D_];
__device__ float g_sufv[(size_t)B_ * H_ * 33 * 64];

// ---------------- helpers ---------------------------------------------------
__device__ __forceinline__ uint32_t smem_u32(const void* p) {
    uint32_t a;
    asm("{ .reg .u64 t; cvta.to.shared.u64 t, %1; cvt.u32.u64 %0, t; }" : "=r"(a) : "l"(p));
    return a;
}
#define CP_ASYNC16(dst, src) \
    asm volatile("cp.async.cg.shared.global [%0], [%1], 16;" :: "r"(dst), "l"(src))
#define CP_COMMIT() asm volatile("cp.async.commit_group;")
#define CP_WAIT0()  asm volatile("cp.async.wait_group 0;")
#define PAIRBAR(p)  asm volatile("bar.sync %0, 64;" :: "r"((p) + 1) : "memory")

// ---------------------------------------------------------------------------
// HMMA GEMM: 128x128 tile, 256 thr, BK=32, 2 CTAs/SM, ONE sync per K-iter.
// ---------------------------------------------------------------------------
#define BM 128
#define BN 128
#define BK 32
#define GP 40
#define MATB (BM * GP * 2)
#define STAGEB (4 * MATB)
#define GSMEM (2 * STAGEB)

template<int MODE>
__global__ void __launch_bounds__(256, 2) gemm_wmma(
    const __nv_bfloat16* __restrict__ Ahi, const __nv_bfloat16* __restrict__ Alo,
    const __nv_bfloat16* __restrict__ Bhi, const __nv_bfloat16* __restrict__ Blo,
    float* __restrict__ C, __nv_bfloat16* __restrict__ Chi,
    __nv_bfloat16* __restrict__ Clo, int M, int N, int K)
{
    extern __shared__ __align__(16) char smem[];
    const uint32_t sb = smem_u32(smem);
    const int tid = threadIdx.x;
    const int wid = tid >> 5;
    const int wm = wid & 3, wn = wid >> 2;
    const int m0 = blockIdx.y * BM, n0 = blockIdx.x * BN;

    wmma::fragment<wmma::accumulator, 16, 16, 16, float> acc[2][4];
#pragma unroll
    for (int i = 0; i < 2; i++)
#pragma unroll
        for (int j = 0; j < 4; j++) wmma::fill_fragment(acc[i][j], 0.0f);

    const int u0 = tid * 2;
    const int lrow = u0 >> 2;
    const int lcb = (u0 & 3) * 16;
    const char* gAh = (const char*)&Ahi[(size_t)(m0 + lrow) * K] + lcb;
    const char* gAl = (const char*)&Alo[(size_t)(m0 + lrow) * K] + lcb;
    const char* gBh = (const char*)&Bhi[(size_t)(n0 + lrow) * K] + lcb;
    const char* gBl = (const char*)&Blo[(size_t)(n0 + lrow) * K] + lcb;
    const uint32_t soff = lrow * (GP * 2) + lcb;

    const int KT = K / BK;
    auto issue = [&](int st, int kt) {
        const uint32_t base = sb + st * STAGEB + soff;
        const size_t gk = (size_t)kt * (BK * 2);
        CP_ASYNC16(base,            gAh + gk);  CP_ASYNC16(base + 16,            gAh + gk + 16);
        CP_ASYNC16(base + MATB,     gAl + gk);  CP_ASYNC16(base + MATB + 16,     gAl + gk + 16);
        CP_ASYNC16(base + 2*MATB,   gBh + gk);  CP_ASYNC16(base + 2*MATB + 16,   gBh + gk + 16);
        CP_ASYNC16(base + 3*MATB,   gBl + gk);  CP_ASYNC16(base + 3*MATB + 16,   gBl + gk + 16);
    };

    issue(0, 0);
    CP_COMMIT();

    for (int kt = 0; kt < KT; kt++) {
        const int st = kt & 1;
        // wait for stage st; the barrier also proves everyone finished
        // reading stage st^1 (last tile's compute), so prefetch may overwrite it
        CP_WAIT0();
        __syncthreads();
        if (kt + 1 < KT) { issue(st ^ 1, kt + 1); CP_COMMIT(); }

        const __nv_bfloat16* sAh = (const __nv_bfloat16*)(smem + st * STAGEB);
        const __nv_bfloat16* sAl = sAh + BM * GP;
        const __nv_bfloat16* sBh = sAl + BM * GP;
        const __nv_bfloat16* sBl = sBh + BM * GP;

#pragma unroll
        for (int kk = 0; kk < BK; kk += 16) {
            wmma::fragment<wmma::matrix_b, 16, 16, 16, __nv_bfloat16, wmma::col_major> bh[4], bl[4];
#pragma unroll
            for (int j = 0; j < 4; j++) {
                wmma::load_matrix_sync(bh[j], sBh + (wn * 64 + j * 16) * GP + kk, GP);
                wmma::load_matrix_sync(bl[j], sBl + (wn * 64 + j * 16) * GP + kk, GP);
            }
#pragma unroll
            for (int i = 0; i < 2; i++) {
                wmma::fragment<wmma::matrix_a, 16, 16, 16, __nv_bfloat16, wmma::row_major> ah, al;
                wmma::load_matrix_sync(ah, sAh + (wm * 32 + i * 16) * GP + kk, GP);
                wmma::load_matrix_sync(al, sAl + (wm * 32 + i * 16) * GP + kk, GP);
#pragma unroll
                for (int j = 0; j < 4; j++) {
                    wmma::mma_sync(acc[i][j], ah, bh[j], acc[i][j]);
                    wmma::mma_sync(acc[i][j], ah, bl[j], acc[i][j]);
                    wmma::mma_sync(acc[i][j], al, bh[j], acc[i][j]);
                }
            }
        }
    }

    if (MODE == 0) {
#pragma unroll
        for (int i = 0; i < 2; i++)
#pragma unroll
            for (int j = 0; j < 4; j++)
                wmma::store_matrix_sync(
                    &C[(size_t)(m0 + wm * 32 + i * 16) * N + n0 + wn * 64 + j * 16],
                    acc[i][j], N, wmma::mem_row_major);
    } else {
        __syncthreads();   // all reads of the stage buffers done before overwrite
        float* stage = (float*)smem;
#pragma unroll
        for (int i = 0; i < 2; i++)
#pragma unroll
            for (int j = 0; j < 4; j++)
                wmma::store_matrix_sync(
                    &stage[(size_t)(wm * 32 + i * 16) * BN + wn * 64 + j * 16],
                    acc[i][j], BN, wmma::mem_row_major);
        __syncthreads();
#pragma unroll
        for (int it = 0; it < 16; it++) {
            const int fi = tid + it * 256;
            const int row = fi >> 5, c4 = (fi & 31) * 4;
            float4 v = *(const float4*)&stage[row * BN + c4];
            __nv_bfloat16 h0 = __float2bfloat16(v.x), h1 = __float2bfloat16(v.y);
            __nv_bfloat16 h2 = __float2bfloat16(v.z), h3 = __float2bfloat16(v.w);
            __nv_bfloat162 hA(h0, h1), hB(h2, h3);
            __nv_bfloat162 lA(__float2bfloat16(v.x - __bfloat162float(h0)),
                              __float2bfloat16(v.y - __bfloat162float(h1)));
            __nv_bfloat162 lB(__float2bfloat16(v.z - __bfloat162float(h2)),
                              __float2bfloat16(v.w - __bfloat162float(h3)));
            const size_t o = (size_t)(m0 + row) * N + n0 + c4;
            *(__nv_bfloat162*)&Chi[o] = hA; *(__nv_bfloat162*)&Chi[o + 2] = hB;
            *(__nv_bfloat162*)&Clo[o] = lA; *(__nv_bfloat162*)&Clo[o + 2] = lB;
        }
    }
}

// ---------------------------------------------------------------------------
__global__ void __launch_bounds__(256) split4(const float4* __restrict__ in,
                                              __nv_bfloat162* __restrict__ hi,
                                              __nv_bfloat162* __restrict__ lo,
                                              int n4) {
    int i = blockIdx.x * 256 + threadIdx.x;
    if (i >= n4) return;
    float4 v = in[i];
    __nv_bfloat16 h0 = __float2bfloat16(v.x), h1 = __float2bfloat16(v.y);
    __nv_bfloat16 h2 = __float2bfloat16(v.z), h3 = __float2bfloat16(v.w);
    hi[i * 2 + 0] = __nv_bfloat162(h0, h1);
    hi[i * 2 + 1] = __nv_bfloat162(h2, h3);
    lo[i * 2 + 0] = __nv_bfloat162(__float2bfloat16(v.x - __bfloat162float(h0)),
                                   __float2bfloat16(v.y - __bfloat162float(h1)));
    lo[i * 2 + 1] = __nv_bfloat162(__float2bfloat16(v.z - __bfloat162float(h2)),
                                   __float2bfloat16(v.w - __bfloat162float(h3)));
}

__global__ void __launch_bounds__(256) transpose_split(const float* __restrict__ W,
                                                       __nv_bfloat16* __restrict__ hi,
                                                       __nv_bfloat16* __restrict__ lo,
                                                       int K, int N) {
    __shared__ float t[32][33];
    const int n0 = blockIdx.x * 32, k0 = blockIdx.y * 32;
    const int x = threadIdx.x, y = threadIdx.y;
#pragma unroll
    for (int i = 0; i < 32; i += 8)
        t[y + i][x] = W[(size_t)(k0 + y + i) * N + n0 + x];
    __syncthreads();
#pragma unroll
    for (int i = 0; i < 32; i += 8) {
        float v = t[x][y + i];
        __nv_bfloat16 h = __float2bfloat16(v);
        size_t o = (size_t)(n0 + y + i) * K + k0 + x;
        hi[o] = h;
        lo[o] = __float2bfloat16(v - __bfloat162float(h));
    }
}

// ---------------------------------------------------------------------------
__global__ void __launch_bounds__(64) sufv_partial(const __nv_bfloat16* __restrict__ qhi,
                                                   const __nv_bfloat16* __restrict__ qlo,
                                                   float* __restrict__ sufv) {
    const int t = blockIdx.x, h = blockIdx.y, b = blockIdx.z, d = threadIdx.x;
    const size_t col = (size_t)h * QKV_ + 128 + d;
    float acc = 0.0f;
#pragma unroll 8
    for (int kk = 0; kk < 64; kk++) {
        const size_t o = (size_t)(b * S_ + t * 64 + kk) * NQKV + col;
        acc += __bfloat162float(qhi[o]) + __bfloat162float(qlo[o]);
    }
    sufv[((size_t)(b * H_ + h) * 33 + t) * 64 + d] = acc;
}

__global__ void __launch_bounds__(64) sufv_scan(float* __restrict__ sufv) {
    const int h = blockIdx.x, b = blockIdx.y, d = threadIdx.x;
    float* base = &sufv[((size_t)(b * H_ + h) * 33) * 64 + d];
    float acc = 0.0f;
    base[32 * 64] = 0.0f;
    for (int t = 31; t >= 0; t--) {
        acc += base[t * 64];
        base[t * 64] = acc;
    }
}

// ---------------------------------------------------------------------------
// wmma flash attention, 512 threads, pair-scoped barriers.
// Warp pair p = {warp p (cols 0-31), warp p+8 (cols 32-63)} owns rows
// [16p, 16p+16). Only the KV-stage sync is block-wide.
// ---------------------------------------------------------------------------
#define AP 72
#define SFP 68
#define AQH 0
#define AQL (AQH + 128 * AP * 2)
#define AKV (AQL + 128 * AP * 2)
#define KVMAT (64 * AP * 2)
#define KVSTAGE (4 * KVMAT)
#define APH (AKV + 2 * KVSTAGE)
#define APL (APH + 128 * AP * 2)
#define ASF (APL + 128 * AP * 2)
#define ASMEM (ASF + 128 * SFP * 4)

__global__ void __launch_bounds__(512) attn_wmma(
    const __nv_bfloat16* __restrict__ qkvhi, const __nv_bfloat16* __restrict__ qkvlo,
    const float* __restrict__ sufv,
    __nv_bfloat16* __restrict__ ahi, __nv_bfloat16* __restrict__ alo)
{
    extern __shared__ __align__(16) char smem[];
    const uint32_t sb = smem_u32(smem);
    __nv_bfloat16* sQh = (__nv_bfloat16*)(smem + AQH);
    __nv_bfloat16* sQl = (__nv_bfloat16*)(smem + AQL);
    __nv_bfloat16* sPh = (__nv_bfloat16*)(smem + APH);
    __nv_bfloat16* sPl = (__nv_bfloat16*)(smem + APL);
    float* sSF = (float*)(smem + ASF);

    const int tid = threadIdx.x, wid = tid >> 5, lane = tid & 31;
    const int pr   = wid & 7;               // pair id
    const int sub  = wid >> 3;              // 0: cols 0-31, 1: cols 32-63
    const int wrow = pr * 16;
    const int wcol = sub * 2;
    const int qt = gridDim.x - 1 - blockIdx.x;     // heavy blocks first
    const int h = blockIdx.y, b = blockIdx.z;
    const int q0 = qt * 128;
    const size_t base = (size_t)b * S_ * NQKV + (size_t)h * QKV_;

    // K/V cp.async loader (block-wide)
    const int krow = tid >> 3, kc8 = (tid & 7) * 8;
    const uint32_t kvoff = (uint32_t)(krow * AP + kc8) * 2;
    auto issue_kv = [&](int st, int kt) {
        const uint32_t stb = sb + AKV + st * KVSTAGE + kvoff;
        const char* gh = (const char*)(qkvhi + base + (size_t)(kt * 64 + krow) * NQKV + kc8);
        const char* gl = (const char*)(qkvlo + base + (size_t)(kt * 64 + krow) * NQKV + kc8);
        CP_ASYNC16(stb,             gh + 128);
        CP_ASYNC16(stb + KVMAT,     gl + 128);
        CP_ASYNC16(stb + 2*KVMAT,   gh + 256);
        CP_ASYNC16(stb + 3*KVMAT,   gl + 256);
    };

    // load Q hi/lo (128 x 64)
#pragma unroll
    for (int j = 0; j < 2; j++) {
        const int i = tid + j * 512;
        const int row = i >> 3, c8 = (i & 7) * 8;
        const size_t g = base + (size_t)(q0 + row) * NQKV + c8;
        *(uint4*)&sQh[row * AP + c8] = *(const uint4*)&qkvhi[g];
        *(uint4*)&sQl[row * AP + c8] = *(const uint4*)&qkvlo[g];
    }

    // softmax mapping: each row's 4 threads live in ONE warp
    const int srow = pr * 16 + sub * 8 + (lane >> 2);
    const int scb  = (lane & 3) * 16;
    float m = -1e30f, l = 0.0f, alpha = 0.0f;
    float o[16];
#pragma unroll
    for (int c = 0; c < 16; c++) o[c] = 0.0f;
    const float scale = 0.125f;
    const int gq = q0 + srow;

    const int KTILES = 2 * qt + 2;
    issue_kv(0, 0);
    CP_COMMIT();

    for (int kt = 0; kt < KTILES; kt++) {
        const int st = kt & 1;
        const int k0 = kt * 64;
        CP_WAIT0();
        __syncthreads();   // stage st visible; stage st^1 reads (tile kt-1) done
        if (kt + 1 < KTILES) { issue_kv(st ^ 1, kt + 1); CP_COMMIT(); }

        const __nv_bfloat16* sKh = (const __nv_bfloat16*)(smem + AKV + st * KVSTAGE);
        const __nv_bfloat16* sKl = sKh + 64 * AP;
        const __nv_bfloat16* sVh = sKl + 64 * AP;
        const __nv_bfloat16* sVl = sVh + 64 * AP;

        // S = Q @ K^T  (warp: 16 rows x 32 keys)
        {
            wmma::fragment<wmma::accumulator, 16, 16, 16, float> sacc[2];
#pragma unroll
            for (int j = 0; j < 2; j++) wmma::fill_fragment(sacc[j], 0.0f);
#pragma unroll
            for (int ks = 0; ks < 4; ks++) {
                const int kk = ks * 16;
                wmma::fragment<wmma::matrix_a, 16, 16, 16, __nv_bfloat16, wmma::row_major> ah, al;
                wmma::load_matrix_sync(ah, sQh + wrow * AP + kk, AP);
                wmma::load_matrix_sync(al, sQl + wrow * AP + kk, AP);
#pragma unroll
                for (int j = 0; j < 2; j++) {
                    wmma::fragment<wmma::matrix_b, 16, 16, 16, __nv_bfloat16, wmma::col_major> bh, bl;
                    wmma::load_matrix_sync(bh, sKh + ((wcol + j) * 16) * AP + kk, AP);
                    wmma::load_matrix_sync(bl, sKl + ((wcol + j) * 16) * AP + kk, AP);
                    wmma::mma_sync(sacc[j], ah, bh, sacc[j]);
                    wmma::mma_sync(sacc[j], ah, bl, sacc[j]);
                    wmma::mma_sync(sacc[j], al, bh, sacc[j]);
                }
            }
#pragma unroll
            for (int j = 0; j < 2; j++)
                wmma::store_matrix_sync(&sSF[wrow * SFP + (wcol + j) * 16], sacc[j],
                                        SFP, wmma::mem_row_major);
        }
        PAIRBAR(pr);

        // mask + online softmax; write P hi/lo (pair-local rows)
        {
            float s[16];
#pragma unroll
            for (int c4 = 0; c4 < 4; c4++) {
                float4 v = *(const float4*)&sSF[srow * SFP + scb + c4 * 4];
                s[c4 * 4 + 0] = v.x; s[c4 * 4 + 1] = v.y;
                s[c4 * 4 + 2] = v.z; s[c4 * 4 + 3] = v.w;
            }
            const int lim = gq - k0;
#pragma unroll
            for (int c = 0; c < 16; c++) {
                float sv = s[c] * scale;
                if (scb + c > lim) sv = 0.0f;
                s[c] = sv;
            }
            float tmax = s[0];
#pragma unroll
            for (int c = 1; c < 16; c++) tmax = fmaxf(tmax, s[c]);
            tmax = fmaxf(tmax, __shfl_xor_sync(0xffffffffu, tmax, 1));
            tmax = fmaxf(tmax, __shfl_xor_sync(0xffffffffu, tmax, 2));
            const float mn = fmaxf(m, tmax);
            alpha = __expf(m - mn);
            m = mn;
            float ps = 0.0f;
#pragma unroll
            for (int c = 0; c < 16; c++) { s[c] = __expf(s[c] - mn); ps += s[c]; }
            ps += __shfl_xor_sync(0xffffffffu, ps, 1);
            ps += __shfl_xor_sync(0xffffffffu, ps, 2);
            l = l * alpha + ps;
#pragma unroll
            for (int c4 = 0; c4 < 2; c4++) {
                __nv_bfloat16 hh[8], ll[8];
#pragma unroll
                for (int e = 0; e < 8; e++) {
                    const float p = s[c4 * 8 + e];
                    hh[e] = __float2bfloat16(p);
                    ll[e] = __float2bfloat16(p - __bfloat162float(hh[e]));
                }
                *(uint4*)&sPh[srow * AP + scb + c4 * 8] = *(const uint4*)hh;
                *(uint4*)&sPl[srow * AP + scb + c4 * 8] = *(const uint4*)ll;
            }
        }
        PAIRBAR(pr);

        // PV = P @ V  (warp: 16 rows x 32 dims)
        {
            wmma::fragment<wmma::accumulator, 16, 16, 16, float> pacc[2];
#pragma unroll
            for (int j = 0; j < 2; j++) wmma::fill_fragment(pacc[j], 0.0f);
#pragma unroll
            for (int ks = 0; ks < 4; ks++) {
                const int kk = ks * 16;
                wmma::fragment<wmma::matrix_a, 16, 16, 16, __nv_bfloat16, wmma::row_major> ah, al;
                wmma::load_matrix_sync(ah, sPh + wrow * AP + kk, AP);
                wmma::load_matrix_sync(al, sPl + wrow * AP + kk, AP);
#pragma unroll
                for (int j = 0; j < 2; j++) {
                    wmma::fragment<wmma::matrix_b, 16, 16, 16, __nv_bfloat16, wmma::row_major> bh, bl;
                    wmma::load_matrix_sync(bh, sVh + kk * AP + (wcol + j) * 16, AP);
                    wmma::load_matrix_sync(bl, sVl + kk * AP + (wcol + j) * 16, AP);
                    wmma::mma_sync(pacc[j], ah, bh, pacc[j]);
                    wmma::mma_sync(pacc[j], ah, bl, pacc[j]);
                    wmma::mma_sync(pacc[j], al, bh, pacc[j]);
                }
            }
#pragma unroll
            for (int j = 0; j < 2; j++)
                wmma::store_matrix_sync(&sSF[wrow * SFP + (wcol + j) * 16], pacc[j],
                                        SFP, wmma::mem_row_major);
        }
        PAIRBAR(pr);

        // O(reg) = O*alpha + PV
#pragma unroll
        for (int c4 = 0; c4 < 4; c4++) {
            float4 p = *(const float4*)&sSF[srow * SFP + scb + c4 * 4];
            o[c4 * 4 + 0] = o[c4 * 4 + 0] * alpha + p.x;
            o[c4 * 4 + 1] = o[c4 * 4 + 1] * alpha + p.y;
            o[c4 * 4 + 2] = o[c4 * 4 + 2] * alpha + p.z;
            o[c4 * 4 + 3] = o[c4 * 4 + 3] * alpha + p.w;
        }
    }

    // suffix keys >= 128*(qt+1): logit 0 each
    const int cnt = S_ - 128 * (qt + 1);
    if (cnt > 0) {
        const float mn = fmaxf(m, 0.0f);
        const float a2 = __expf(m - mn);
        const float e0 = __expf(-mn);
        l = l * a2 + (float)cnt * e0;
        const float* sv = &sufv[((size_t)(b * H_ + h) * 33 + 2 * (qt + 1)) * 64 + scb];
#pragma unroll
        for (int c = 0; c < 16; c++) o[c] = o[c] * a2 + e0 * sv[c];
    }
    const float inv = 1.0f / l;
    const size_t orow = (size_t)(b * S_ + q0 + srow) * D_ + h * 64 + scb;
#pragma unroll
    for (int c4 = 0; c4 < 2; c4++) {
        __nv_bfloat16 hh[8], ll[8];
#pragma unroll
        for (int e = 0; e < 8; e++) {
            const float v = o[c4 * 8 + e] * inv;
            hh[e] = __float2bfloat16(v);
            ll[e] = __float2bfloat16(v - __bfloat162float(hh[e]));
        }
        *(uint4*)&ahi[orow + c4 * 8] = *(const uint4*)hh;
        *(uint4*)&alo[orow + c4 * 8] = *(const uint4*)ll;
    }
}

// ---------------------------------------------------------------------------
__global__ void __launch_bounds__(256) ln_kernel(const float* __restrict__ x,
                                                 const float* __restrict__ y,
                                                 const float* __restrict__ gamma,
                                                 const float* __restrict__ beta,
                                                 float* __restrict__ out) {
    __shared__ float red[8];
    const int row = blockIdx.x, t = threadIdx.x;
    const int lane = t & 31, wid = t >> 5;
    const size_t off = (size_t)row * D_;

    float v[4], s = 0.0f;
#pragma unroll
    for (int i = 0; i < 4; i++) {
        int idx = t + i * 256;
        v[i] = x[off + idx] + y[off + idx];
        s += v[i];
    }
    for (int d = 16; d > 0; d >>= 1) s += __shfl_xor_sync(0xffffffffu, s, d);
    if (lane == 0) red[wid] = s;
    __syncthreads();
    float tot = 0.0f;
#pragma unroll
    for (int w = 0; w < 8; w++) tot += red[w];
    const float mean = tot * (1.0f / D_);
    __syncthreads();
    float ss = 0.0f;
#pragma unroll
    for (int i = 0; i < 4; i++) { float d = v[i] - mean; ss += d * d; }
    for (int d = 16; d > 0; d >>= 1) ss += __shfl_xor_sync(0xffffffffu, ss, d);
    if (lane == 0) red[wid] = ss;
    __syncthreads();
    float tot2 = 0.0f;
#pragma unroll
    for (int w = 0; w < 8; w++) tot2 += red[w];
    const float rstd = rsqrtf(tot2 * (1.0f / D_) + 1e-3f);
#pragma unroll
    for (int i = 0; i < 4; i++) {
        int idx = t + i * 256;
        out[off + idx] = (v[i] - mean) * rstd * gamma[idx] + beta[idx];
    }
}

// ---------------------------------------------------------------------------
extern "C" void kernel_launch(void* const* d_in, const int* in_sizes, int n_in,
                              void* d_out, int out_size) {
    const float* x       = (const float*)d_in[0];
    const float* W_embed = (const float*)d_in[2];
    const float* W_out   = (const float*)d_in[3];
    const float* gamma   = (const float*)d_in[4];
    const float* beta    = (const float*)d_in[5];
    float* out = (float*)d_out;

    __nv_bfloat16 *qhi, *qlo, *xhi, *xlo, *wehi, *welo, *wohi, *wolo, *ahi, *alo;
    float *y, *sufv;
    cudaGetSymbolAddress((void**)&qhi,  g_qkvhi);
    cudaGetSymbolAddress((void**)&qlo,  g_qkvlo);
    cudaGetSymbolAddress((void**)&xhi,  g_xhi);
    cudaGetSymbolAddress((void**)&xlo,  g_xlo);
    cudaGetSymbolAddress((void**)&wehi, g_wehi);
    cudaGetSymbolAddress((void**)&welo, g_welo);
    cudaGetSymbolAddress((void**)&wohi, g_wohi);
    cudaGetSymbolAddress((void**)&wolo, g_wolo);
    cudaGetSymbolAddress((void**)&ahi,  g_ahi);
    cudaGetSymbolAddress((void**)&alo,  g_alo);
    cudaGetSymbolAddress((void**)&y,    g_y);
    cudaGetSymbolAddress((void**)&sufv, g_sufv);

    cudaFuncSetAttribute(gemm_wmma<0>, cudaFuncAttributeMaxDynamicSharedMemorySize, GSMEM);
    cudaFuncSetAttribute(gemm_wmma<1>, cudaFuncAttributeMaxDynamicSharedMemorySize, GSMEM);
    cudaFuncSetAttribute(attn_wmma, cudaFuncAttributeMaxDynamicSharedMemorySize, ASMEM);

    split4<<<(MROWS * D_ / 4 + 255) / 256, 256>>>((const float4*)x,
        (__nv_bfloat162*)xhi, (__nv_bfloat162*)xlo, MROWS * D_ / 4);
    transpose_split<<<dim3(NQKV / 32, D_ / 32), dim3(32, 8)>>>(W_embed, wehi, welo, D_, NQKV);
    transpose_split<<<dim3(D_ / 32, D_ / 32), dim3(32, 8)>>>(W_out, wohi, wolo, D_, D_);

    gemm_wmma<1><<<dim3(NQKV / BN, MROWS / BM), 256, GSMEM>>>(
        xhi, xlo, wehi, welo, nullptr, qhi, qlo, MROWS, NQKV, D_);

    sufv_partial<<<dim3(32, H_, B_), 64>>>(qhi, qlo, sufv);
    sufv_scan<<<dim3(H_, B_), 64>>>(sufv);

    attn_wmma<<<dim3(S_ / 128, H_, B_), 512, ASMEM>>>(qhi, qlo, sufv, ahi, alo);

    gemm_wmma<0><<<dim3(D_ / BN, MROWS / BM), 256, GSMEM>>>(
        ahi, alo, wohi, wolo, y, nullptr, nullptr, MROWS, D_, D_);

    ln_kernel<<<MROWS, 256>>>(x, y, gamma, beta, out);
}

// round 11
// speedup vs baseline: 1.0760x; 1.0760x over previous
#include <cuda_runtime.h>
#include <cuda_bf16.h>
#include <mma.h>
#include <cstdint>
#include <math.h>

using namespace nvcuda;

#define B_    2
#define S_    2048
#define D_    1024
#define H_    16
#define QKV_  192
#define NQKV  (H_ * QKV_)   /* 3072 */
#define MROWS (B_ * S_)     /* 4096 */

// ---------------- scratch ---------------------------------------------------
__device__ __nv_bfloat16 g_qkvhi[(size_t)MROWS * NQKV];
__device__ __nv_bfloat16 g_qkvlo[(size_t)MROWS * NQKV];
__device__ __nv_bfloat16 g_xhi[(size_t)MROWS * D_];
__device__ __nv_bfloat16 g_xlo[(size_t)MROWS * D_];
__device__ __nv_bfloat16 g_wehi[(size_t)NQKV * D_];   // [N][K]
__device__ __nv_bfloat16 g_welo[(size_t)NQKV * D_];
__device__ __nv_bfloat16 g_wohi[(size_t)D_ * D_];
__device__ __nv_bfloat16 g_wolo[(size_t)D_ * D_];
__device__ __nv_bfloat16 g_ahi[(size_t)MROWS * D_];
__device__ __nv_bfloat16 g_alo[(size_t)MROWS * D_];
__device__ float g_y[(size_t)MROWS * D_];
__device__ float g_sufv[(size_t)B_ * H_ * 33 * 64];

// ---------------- helpers ---------------------------------------------------
__device__ __forceinline__ uint32_t smem_u32(const void* p) {
    uint32_t a;
    asm("{ .reg .u64 t; cvta.to.shared.u64 t, %1; cvt.u32.u64 %0, t; }" : "=r"(a) : "l"(p));
    return a;
}
#define CP_ASYNC16(dst, src) \
    asm volatile("cp.async.cg.shared.global [%0], [%1], 16;" :: "r"(dst), "l"(src))
#define CP_COMMIT() asm volatile("cp.async.commit_group;")
#define CP_WAIT0()  asm volatile("cp.async.wait_group 0;")

// ---------------------------------------------------------------------------
// HMMA GEMM (R10 version — one sync per K-iter, 2 CTAs/SM). UNCHANGED.
// ---------------------------------------------------------------------------
#define BM 128
#define BN 128
#define BK 32
#define GP 40
#define MATB (BM * GP * 2)
#define STAGEB (4 * MATB)
#define GSMEM (2 * STAGEB)

template<int MODE>
__global__ void __launch_bounds__(256, 2) gemm_wmma(
    const __nv_bfloat16* __restrict__ Ahi, const __nv_bfloat16* __restrict__ Alo,
    const __nv_bfloat16* __restrict__ Bhi, const __nv_bfloat16* __restrict__ Blo,
    float* __restrict__ C, __nv_bfloat16* __restrict__ Chi,
    __nv_bfloat16* __restrict__ Clo, int M, int N, int K)
{
    extern __shared__ __align__(16) char smem[];
    const uint32_t sb = smem_u32(smem);
    const int tid = threadIdx.x;
    const int wid = tid >> 5;
    const int wm = wid & 3, wn = wid >> 2;
    const int m0 = blockIdx.y * BM, n0 = blockIdx.x * BN;

    wmma::fragment<wmma::accumulator, 16, 16, 16, float> acc[2][4];
#pragma unroll
    for (int i = 0; i < 2; i++)
#pragma unroll
        for (int j = 0; j < 4; j++) wmma::fill_fragment(acc[i][j], 0.0f);

    const int u0 = tid * 2;
    const int lrow = u0 >> 2;
    const int lcb = (u0 & 3) * 16;
    const char* gAh = (const char*)&Ahi[(size_t)(m0 + lrow) * K] + lcb;
    const char* gAl = (const char*)&Alo[(size_t)(m0 + lrow) * K] + lcb;
    const char* gBh = (const char*)&Bhi[(size_t)(n0 + lrow) * K] + lcb;
    const char* gBl = (const char*)&Blo[(size_t)(n0 + lrow) * K] + lcb;
    const uint32_t soff = lrow * (GP * 2) + lcb;

    const int KT = K / BK;
    auto issue = [&](int st, int kt) {
        const uint32_t base = sb + st * STAGEB + soff;
        const size_t gk = (size_t)kt * (BK * 2);
        CP_ASYNC16(base,            gAh + gk);  CP_ASYNC16(base + 16,            gAh + gk + 16);
        CP_ASYNC16(base + MATB,     gAl + gk);  CP_ASYNC16(base + MATB + 16,     gAl + gk + 16);
        CP_ASYNC16(base + 2*MATB,   gBh + gk);  CP_ASYNC16(base + 2*MATB + 16,   gBh + gk + 16);
        CP_ASYNC16(base + 3*MATB,   gBl + gk);  CP_ASYNC16(base + 3*MATB + 16,   gBl + gk + 16);
    };

    issue(0, 0);
    CP_COMMIT();

    for (int kt = 0; kt < KT; kt++) {
        const int st = kt & 1;
        CP_WAIT0();
        __syncthreads();
        if (kt + 1 < KT) { issue(st ^ 1, kt + 1); CP_COMMIT(); }

        const __nv_bfloat16* sAh = (const __nv_bfloat16*)(smem + st * STAGEB);
        const __nv_bfloat16* sAl = sAh + BM * GP;
        const __nv_bfloat16* sBh = sAl + BM * GP;
        const __nv_bfloat16* sBl = sBh + BM * GP;

#pragma unroll
        for (int kk = 0; kk < BK; kk += 16) {
            wmma::fragment<wmma::matrix_b, 16, 16, 16, __nv_bfloat16, wmma::col_major> bh[4], bl[4];
#pragma unroll
            for (int j = 0; j < 4; j++) {
                wmma::load_matrix_sync(bh[j], sBh + (wn * 64 + j * 16) * GP + kk, GP);
                wmma::load_matrix_sync(bl[j], sBl + (wn * 64 + j * 16) * GP + kk, GP);
            }
#pragma unroll
            for (int i = 0; i < 2; i++) {
                wmma::fragment<wmma::matrix_a, 16, 16, 16, __nv_bfloat16, wmma::row_major> ah, al;
                wmma::load_matrix_sync(ah, sAh + (wm * 32 + i * 16) * GP + kk, GP);
                wmma::load_matrix_sync(al, sAl + (wm * 32 + i * 16) * GP + kk, GP);
#pragma unroll
                for (int j = 0; j < 4; j++) {
                    wmma::mma_sync(acc[i][j], ah, bh[j], acc[i][j]);
                    wmma::mma_sync(acc[i][j], ah, bl[j], acc[i][j]);
                    wmma::mma_sync(acc[i][j], al, bh[j], acc[i][j]);
                }
            }
        }
    }

    if (MODE == 0) {
#pragma unroll
        for (int i = 0; i < 2; i++)
#pragma unroll
            for (int j = 0; j < 4; j++)
                wmma::store_matrix_sync(
                    &C[(size_t)(m0 + wm * 32 + i * 16) * N + n0 + wn * 64 + j * 16],
                    acc[i][j], N, wmma::mem_row_major);
    } else {
        __syncthreads();
        float* stage = (float*)smem;
#pragma unroll
        for (int i = 0; i < 2; i++)
#pragma unroll
            for (int j = 0; j < 4; j++)
                wmma::store_matrix_sync(
                    &stage[(size_t)(wm * 32 + i * 16) * BN + wn * 64 + j * 16],
                    acc[i][j], BN, wmma::mem_row_major);
        __syncthreads();
#pragma unroll
        for (int it = 0; it < 16; it++) {
            const int fi = tid + it * 256;
            const int row = fi >> 5, c4 = (fi & 31) * 4;
            float4 v = *(const float4*)&stage[row * BN + c4];
            __nv_bfloat16 h0 = __float2bfloat16(v.x), h1 = __float2bfloat16(v.y);
            __nv_bfloat16 h2 = __float2bfloat16(v.z), h3 = __float2bfloat16(v.w);
            __nv_bfloat162 hA(h0, h1), hB(h2, h3);
            __nv_bfloat162 lA(__float2bfloat16(v.x - __bfloat162float(h0)),
                              __float2bfloat16(v.y - __bfloat162float(h1)));
            __nv_bfloat162 lB(__float2bfloat16(v.z - __bfloat162float(h2)),
                              __float2bfloat16(v.w - __bfloat162float(h3)));
            const size_t o = (size_t)(m0 + row) * N + n0 + c4;
            *(__nv_bfloat162*)&Chi[o] = hA; *(__nv_bfloat162*)&Chi[o + 2] = hB;
            *(__nv_bfloat162*)&Clo[o] = lA; *(__nv_bfloat162*)&Clo[o + 2] = lB;
        }
    }
}

// ---------------------------------------------------------------------------
__global__ void __launch_bounds__(256) split4(const float4* __restrict__ in,
                                              __nv_bfloat162* __restrict__ hi,
                                              __nv_bfloat162* __restrict__ lo,
                                              int n4) {
    int i = blockIdx.x * 256 + threadIdx.x;
    if (i >= n4) return;
    float4 v = in[i];
    __nv_bfloat16 h0 = __float2bfloat16(v.x), h1 = __float2bfloat16(v.y);
    __nv_bfloat16 h2 = __float2bfloat16(v.z), h3 = __float2bfloat16(v.w);
    hi[i * 2 + 0] = __nv_bfloat162(h0, h1);
    hi[i * 2 + 1] = __nv_bfloat162(h2, h3);
    lo[i * 2 + 0] = __nv_bfloat162(__float2bfloat16(v.x - __bfloat162float(h0)),
                                   __float2bfloat16(v.y - __bfloat162float(h1)));
    lo[i * 2 + 1] = __nv_bfloat162(__float2bfloat16(v.z - __bfloat162float(h2)),
                                   __float2bfloat16(v.w - __bfloat162float(h3)));
}

__global__ void __launch_bounds__(256) transpose_split(const float* __restrict__ W,
                                                       __nv_bfloat16* __restrict__ hi,
                                                       __nv_bfloat16* __restrict__ lo,
                                                       int K, int N) {
    __shared__ float t[32][33];
    const int n0 = blockIdx.x * 32, k0 = blockIdx.y * 32;
    const int x = threadIdx.x, y = threadIdx.y;
#pragma unroll
    for (int i = 0; i < 32; i += 8)
        t[y + i][x] = W[(size_t)(k0 + y + i) * N + n0 + x];
    __syncthreads();
#pragma unroll
    for (int i = 0; i < 32; i += 8) {
        float v = t[x][y + i];
        __nv_bfloat16 h = __float2bfloat16(v);
        size_t o = (size_t)(n0 + y + i) * K + k0 + x;
        hi[o] = h;
        lo[o] = __float2bfloat16(v - __bfloat162float(h));
    }
}

// ---------------------------------------------------------------------------
__global__ void __launch_bounds__(64) sufv_partial(const __nv_bfloat16* __restrict__ qhi,
                                                   const __nv_bfloat16* __restrict__ qlo,
                                                   float* __restrict__ sufv) {
    const int t = blockIdx.x, h = blockIdx.y, b = blockIdx.z, d = threadIdx.x;
    const size_t col = (size_t)h * QKV_ + 128 + d;
    float acc = 0.0f;
#pragma unroll 8
    for (int kk = 0; kk < 64; kk++) {
        const size_t o = (size_t)(b * S_ + t * 64 + kk) * NQKV + col;
        acc += __bfloat162float(qhi[o]) + __bfloat162float(qlo[o]);
    }
    sufv[((size_t)(b * H_ + h) * 33 + t) * 64 + d] = acc;
}

__global__ void __launch_bounds__(64) sufv_scan(float* __restrict__ sufv) {
    const int h = blockIdx.x, b = blockIdx.y, d = threadIdx.x;
    float* base = &sufv[((size_t)(b * H_ + h) * 33) * 64 + d];
    float acc = 0.0f;
    base[32 * 64] = 0.0f;
    for (int t = 31; t >= 0; t--) {
        acc += base[t * 64];
        base[t * 64] = acc;
    }
}

// ---------------------------------------------------------------------------
// wmma flash attention, 256 threads, 64-row Q tiles, 2 CTAs/SM.
// smem 109568 B: Q(18432) + KV 2 stages(73728) + SF(17408).
// P hi/lo overlaid into SF rows (272B row >= 128+128B P).
// PV fp32 staging overlaid onto the dead K region of the current stage.
// ---------------------------------------------------------------------------
#define AP 72
#define SFP 68            /* fp32 pitch; 272B rows; bf16 P pitch = 136 */
#define AQH 0
#define AQL (AQH + 64 * AP * 2)            /* 9216  */
#define AKV (AQL + 64 * AP * 2)            /* 18432 */
#define KVMAT (64 * AP * 2)                /* 9216  */
#define KVSTAGE (4 * KVMAT)                /* 36864 */
#define ASF (AKV + 2 * KVSTAGE)            /* 92160 */
#define ASMEM (ASF + 64 * SFP * 4)         /* 109568 */

__global__ void __launch_bounds__(256, 2) attn_wmma(
    const __nv_bfloat16* __restrict__ qkvhi, const __nv_bfloat16* __restrict__ qkvlo,
    const float* __restrict__ sufv,
    __nv_bfloat16* __restrict__ ahi, __nv_bfloat16* __restrict__ alo)
{
    extern __shared__ __align__(32) char smem[];
    const uint32_t sb = smem_u32(smem);
    __nv_bfloat16* sQh = (__nv_bfloat16*)(smem + AQH);
    __nv_bfloat16* sQl = (__nv_bfloat16*)(smem + AQL);
    float* sSF = (float*)(smem + ASF);

    const int tid = threadIdx.x, wid = tid >> 5;
    const int pr  = wid & 3;              // 16-row band
    const int sub = wid >> 2;             // col half (2 j-frags)
    const int wrow = pr * 16;
    const int wcol = sub * 2;
    const int qt = gridDim.x - 1 - blockIdx.x;   // heavy blocks first
    const int h = blockIdx.y, b = blockIdx.z;
    const int q0 = qt * 64;
    const size_t base = (size_t)b * S_ * NQKV + (size_t)h * QKV_;

    // K/V cp.async loader: 2 uint4 per matrix per thread (rows tid>>3 and +32)
    auto issue_kv = [&](int st, int kt) {
#pragma unroll
        for (int jj = 0; jj < 2; jj++) {
            const int row = (tid >> 3) + jj * 32;
            const int c8 = (tid & 7) * 8;
            const uint32_t stb = sb + AKV + st * KVSTAGE + (uint32_t)(row * AP + c8) * 2;
            const char* gh = (const char*)(qkvhi + base + (size_t)(kt * 64 + row) * NQKV + c8);
            const char* gl = (const char*)(qkvlo + base + (size_t)(kt * 64 + row) * NQKV + c8);
            CP_ASYNC16(stb,             gh + 128);   // K hi
            CP_ASYNC16(stb + KVMAT,     gl + 128);   // K lo
            CP_ASYNC16(stb + 2*KVMAT,   gh + 256);   // V hi
            CP_ASYNC16(stb + 3*KVMAT,   gl + 256);   // V lo
        }
    };

    // load Q hi/lo (64 x 64): 512 uint4 per matrix, 2 per thread
#pragma unroll
    for (int j = 0; j < 2; j++) {
        const int i = tid + j * 256;
        const int row = i >> 3, c8 = (i & 7) * 8;
        const size_t g = base + (size_t)(q0 + row) * NQKV + c8;
        *(uint4*)&sQh[row * AP + c8] = *(const uint4*)&qkvhi[g];
        *(uint4*)&sQl[row * AP + c8] = *(const uint4*)&qkvlo[g];
    }

    const int srow = tid >> 2;            // 0..63
    const int scb  = (tid & 3) * 16;      // 16-col quarter
    float m = -1e30f, l = 0.0f, alpha = 0.0f;
    float o[16];
#pragma unroll
    for (int c = 0; c < 16; c++) o[c] = 0.0f;
    const float scale = 0.125f;
    const int gq = q0 + srow;

    const int KTILES = qt + 1;
    issue_kv(0, 0);
    CP_COMMIT();

    for (int kt = 0; kt < KTILES; kt++) {
        const int st = kt & 1;
        const int k0 = kt * 64;
        CP_WAIT0();
        __syncthreads();   // stage st visible; Q visible (kt==0); prev-iter reads done
        if (kt + 1 < KTILES) { issue_kv(st ^ 1, kt + 1); CP_COMMIT(); }

        const __nv_bfloat16* sKh = (const __nv_bfloat16*)(smem + AKV + st * KVSTAGE);
        const __nv_bfloat16* sKl = sKh + 64 * AP;
        const __nv_bfloat16* sVh = sKl + 64 * AP;
        const __nv_bfloat16* sVl = sVh + 64 * AP;
        float* sPV = (float*)(smem + AKV + st * KVSTAGE);   // dead-K overlay

        // S = Q @ K^T  (warp: 16 rows x 32 keys)
        {
            wmma::fragment<wmma::accumulator, 16, 16, 16, float> sacc[2];
#pragma unroll
            for (int j = 0; j < 2; j++) wmma::fill_fragment(sacc[j], 0.0f);
#pragma unroll
            for (int ks = 0; ks < 4; ks++) {
                const int kk = ks * 16;
                wmma::fragment<wmma::matrix_a, 16, 16, 16, __nv_bfloat16, wmma::row_major> ah, al;
                wmma::load_matrix_sync(ah, sQh + wrow * AP + kk, AP);
                wmma::load_matrix_sync(al, sQl + wrow * AP + kk, AP);
#pragma unroll
                for (int j = 0; j < 2; j++) {
                    wmma::fragment<wmma::matrix_b, 16, 16, 16, __nv_bfloat16, wmma::col_major> bh, bl;
                    wmma::load_matrix_sync(bh, sKh + ((wcol + j) * 16) * AP + kk, AP);
                    wmma::load_matrix_sync(bl, sKl + ((wcol + j) * 16) * AP + kk, AP);
                    wmma::mma_sync(sacc[j], ah, bh, sacc[j]);
                    wmma::mma_sync(sacc[j], ah, bl, sacc[j]);
                    wmma::mma_sync(sacc[j], al, bh, sacc[j]);
                }
            }
#pragma unroll
            for (int j = 0; j < 2; j++)
                wmma::store_matrix_sync(&sSF[wrow * SFP + (wcol + j) * 16], sacc[j],
                                        SFP, wmma::mem_row_major);
        }
        __syncthreads();   // S complete (also: K now dead -> PV overlay legal)

        // mask + online softmax; write P hi/lo INTO the SF row footprint.
        // Safe: row r's 4 lanes share one warp; shfl.sync orders all S loads
        // before any P store.
        {
            float s[16];
#pragma unroll
            for (int c4 = 0; c4 < 4; c4++) {
                float4 v = *(const float4*)&sSF[srow * SFP + scb + c4 * 4];
                s[c4 * 4 + 0] = v.x; s[c4 * 4 + 1] = v.y;
                s[c4 * 4 + 2] = v.z; s[c4 * 4 + 3] = v.w;
            }
            const int lim = gq - k0;
#pragma unroll
            for (int c = 0; c < 16; c++) {
                float sv = s[c] * scale;
                if (scb + c > lim) sv = 0.0f;
                s[c] = sv;
            }
            float tmax = s[0];
#pragma unroll
            for (int c = 1; c < 16; c++) tmax = fmaxf(tmax, s[c]);
            tmax = fmaxf(tmax, __shfl_xor_sync(0xffffffffu, tmax, 1));
            tmax = fmaxf(tmax, __shfl_xor_sync(0xffffffffu, tmax, 2));
            const float mn = fmaxf(m, tmax);
            alpha = __expf(m - mn);
            m = mn;
            float ps = 0.0f;
#pragma unroll
            for (int c = 0; c < 16; c++) { s[c] = __expf(s[c] - mn); ps += s[c]; }
            ps += __shfl_xor_sync(0xffffffffu, ps, 1);
            ps += __shfl_xor_sync(0xffffffffu, ps, 2);
            l = l * alpha + ps;
            // P hi at element [srow*136 + scb], P lo at [srow*136 + 64 + scb]
            __nv_bfloat16* sP = (__nv_bfloat16*)sSF;
#pragma unroll
            for (int c4 = 0; c4 < 2; c4++) {
                __nv_bfloat16 hh[8], ll[8];
#pragma unroll
                for (int e = 0; e < 8; e++) {
                    const float p = s[c4 * 8 + e];
                    hh[e] = __float2bfloat16(p);
                    ll[e] = __float2bfloat16(p - __bfloat162float(hh[e]));
                }
                *(uint4*)&sP[srow * 136 + scb + c4 * 8]      = *(const uint4*)hh;
                *(uint4*)&sP[srow * 136 + 64 + scb + c4 * 8] = *(const uint4*)ll;
            }
        }
        __syncthreads();   // P complete

        // PV = P @ V (warp: 16 rows x 32 dims); stage result into dead-K region
        {
            const __nv_bfloat16* sPh = (const __nv_bfloat16*)sSF;        // pitch 136
            const __nv_bfloat16* sPl = ((const __nv_bfloat16*)sSF) + 64;
            wmma::fragment<wmma::accumulator, 16, 16, 16, float> pacc[2];
#pragma unroll
            for (int j = 0; j < 2; j++) wmma::fill_fragment(pacc[j], 0.0f);
#pragma unroll
            for (int ks = 0; ks < 4; ks++) {
                const int kk = ks * 16;
                wmma::fragment<wmma::matrix_a, 16, 16, 16, __nv_bfloat16, wmma::row_major> ah, al;
                wmma::load_matrix_sync(ah, sPh + wrow * 136 + kk, 136);
                wmma::load_matrix_sync(al, sPl + wrow * 136 + kk, 136);
#pragma unroll
                for (int j = 0; j < 2; j++) {
                    wmma::fragment<wmma::matrix_b, 16, 16, 16, __nv_bfloat16, wmma::row_major> bh, bl;
                    wmma::load_matrix_sync(bh, sVh + kk * AP + (wcol + j) * 16, AP);
                    wmma::load_matrix_sync(bl, sVl + kk * AP + (wcol + j) * 16, AP);
                    wmma::mma_sync(pacc[j], ah, bh, pacc[j]);
                    wmma::mma_sync(pacc[j], ah, bl, pacc[j]);
                    wmma::mma_sync(pacc[j], al, bh, pacc[j]);
                }
            }
#pragma unroll
            for (int j = 0; j < 2; j++)
                wmma::store_matrix_sync(&sPV[wrow * SFP + (wcol + j) * 16], pacc[j],
                                        SFP, wmma::mem_row_major);
        }
        __syncthreads();   // PV staged

        // O(reg) = O*alpha + PV
#pragma unroll
        for (int c4 = 0; c4 < 4; c4++) {
            float4 p = *(const float4*)&sPV[srow * SFP + scb + c4 * 4];
            o[c4 * 4 + 0] = o[c4 * 4 + 0] * alpha + p.x;
            o[c4 * 4 + 1] = o[c4 * 4 + 1] * alpha + p.y;
            o[c4 * 4 + 2] = o[c4 * 4 + 2] * alpha + p.z;
            o[c4 * 4 + 3] = o[c4 * 4 + 3] * alpha + p.w;
        }
    }

    // suffix keys >= 64*(qt+1): logit 0 each
    const int cnt = S_ - 64 * (qt + 1);
    if (cnt > 0) {
        const float mn = fmaxf(m, 0.0f);
        const float a2 = __expf(m - mn);
        const float e0 = __expf(-mn);
        l = l * a2 + (float)cnt * e0;
        const float* sv = &sufv[((size_t)(b * H_ + h) * 33 + qt + 1) * 64 + scb];
#pragma unroll
        for (int c = 0; c < 16; c++) o[c] = o[c] * a2 + e0 * sv[c];
    }
    const float inv = 1.0f / l;
    const size_t orow = (size_t)(b * S_ + q0 + srow) * D_ + h * 64 + scb;
#pragma unroll
    for (int c4 = 0; c4 < 2; c4++) {
        __nv_bfloat16 hh[8], ll[8];
#pragma unroll
        for (int e = 0; e < 8; e++) {
            const float v = o[c4 * 8 + e] * inv;
            hh[e] = __float2bfloat16(v);
            ll[e] = __float2bfloat16(v - __bfloat162float(hh[e]));
        }
        *(uint4*)&ahi[orow + c4 * 8] = *(const uint4*)hh;
        *(uint4*)&alo[orow + c4 * 8] = *(const uint4*)ll;
    }
}

// ---------------------------------------------------------------------------
__global__ void __launch_bounds__(256) ln_kernel(const float* __restrict__ x,
                                                 const float* __restrict__ y,
                                                 const float* __restrict__ gamma,
                                                 const float* __restrict__ beta,
                                                 float* __restrict__ out) {
    __shared__ float red[8];
    const int row = blockIdx.x, t = threadIdx.x;
    const int lane = t & 31, wid = t >> 5;
    const size_t off = (size_t)row * D_;

    float v[4], s = 0.0f;
#pragma unroll
    for (int i = 0; i < 4; i++) {
        int idx = t + i * 256;
        v[i] = x[off + idx] + y[off + idx];
        s += v[i];
    }
    for (int d = 16; d > 0; d >>= 1) s += __shfl_xor_sync(0xffffffffu, s, d);
    if (lane == 0) red[wid] = s;
    __syncthreads();
    float tot = 0.0f;
#pragma unroll
    for (int w = 0; w < 8; w++) tot += red[w];
    const float mean = tot * (1.0f / D_);
    __syncthreads();
    float ss = 0.0f;
#pragma unroll
    for (int i = 0; i < 4; i++) { float d = v[i] - mean; ss += d * d; }
    for (int d = 16; d > 0; d >>= 1) ss += __shfl_xor_sync(0xffffffffu, ss, d);
    if (lane == 0) red[wid] = ss;
    __syncthreads();
    float tot2 = 0.0f;
#pragma unroll
    for (int w = 0; w < 8; w++) tot2 += red[w];
    const float rstd = rsqrtf(tot2 * (1.0f / D_) + 1e-3f);
#pragma unroll
    for (int i = 0; i < 4; i++) {
        int idx = t + i * 256;
        out[off + idx] = (v[i] - mean) * rstd * gamma[idx] + beta[idx];
    }
}

// ---------------------------------------------------------------------------
extern "C" void kernel_launch(void* const* d_in, const int* in_sizes, int n_in,
                              void* d_out, int out_size) {
    const float* x       = (const float*)d_in[0];
    const float* W_embed = (const float*)d_in[2];
    const float* W_out   = (const float*)d_in[3];
    const float* gamma   = (const float*)d_in[4];
    const float* beta    = (const float*)d_in[5];
    float* out = (float*)d_out;

    __nv_bfloat16 *qhi, *qlo, *xhi, *xlo, *wehi, *welo, *wohi, *wolo, *ahi, *alo;
    float *y, *sufv;
    cudaGetSymbolAddress((void**)&qhi,  g_qkvhi);
    cudaGetSymbolAddress((void**)&qlo,  g_qkvlo);
    cudaGetSymbolAddress((void**)&xhi,  g_xhi);
    cudaGetSymbolAddress((void**)&xlo,  g_xlo);
    cudaGetSymbolAddress((void**)&wehi, g_wehi);
    cudaGetSymbolAddress((void**)&welo, g_welo);
    cudaGetSymbolAddress((void**)&wohi, g_wohi);
    cudaGetSymbolAddress((void**)&wolo, g_wolo);
    cudaGetSymbolAddress((void**)&ahi,  g_ahi);
    cudaGetSymbolAddress((void**)&alo,  g_alo);
    cudaGetSymbolAddress((void**)&y,    g_y);
    cudaGetSymbolAddress((void**)&sufv, g_sufv);

    cudaFuncSetAttribute(gemm_wmma<0>, cudaFuncAttributeMaxDynamicSharedMemorySize, GSMEM);
    cudaFuncSetAttribute(gemm_wmma<1>, cudaFuncAttributeMaxDynamicSharedMemorySize, GSMEM);
    cudaFuncSetAttribute(attn_wmma, cudaFuncAttributeMaxDynamicSharedMemorySize, ASMEM);

    split4<<<(MROWS * D_ / 4 + 255) / 256, 256>>>((const float4*)x,
        (__nv_bfloat162*)xhi, (__nv_bfloat162*)xlo, MROWS * D_ / 4);
    transpose_split<<<dim3(NQKV / 32, D_ / 32), dim3(32, 8)>>>(W_embed, wehi, welo, D_, NQKV);
    transpose_split<<<dim3(D_ / 32, D_ / 32), dim3(32, 8)>>>(W_out, wohi, wolo, D_, D_);

    gemm_wmma<1><<<dim3(NQKV / BN, MROWS / BM), 256, GSMEM>>>(
        xhi, xlo, wehi, welo, nullptr, qhi, qlo, MROWS, NQKV, D_);

    sufv_partial<<<dim3(32, H_, B_), 64>>>(qhi, qlo, sufv);
    sufv_scan<<<dim3(H_, B_), 64>>>(sufv);

    // 64-row Q tiles now: 32 x H x B grid
    attn_wmma<<<dim3(S_ / 64, H_, B_), 256, ASMEM>>>(qhi, qlo, sufv, ahi, alo);

    gemm_wmma<0><<<dim3(D_ / BN, MROWS / BM), 256, GSMEM>>>(
        ahi, alo, wohi, wolo, y, nullptr, nullptr, MROWS, D_, D_);

    ln_kernel<<<MROWS, 256>>>(x, y, gamma, beta, out);
}